// round 1
// baseline (speedup 1.0000x reference)
#include <cuda_runtime.h>
#include <math.h>

#define NN 20000
#define NE 640000
#define NB 4
#define NS 12
#define HD 64
#define DEG_CAP 128
#define FULL 0xffffffffu

// ---------------- scratch (static device globals; no allocs) ----------------
__device__ float g_h [NB * NN * HD];   // node features (in-place across layers)
__device__ float g_xe[NB * NN * HD];   // per-layer transformed features
__device__ float g_es[NB * NN * 8];    // alpha_src per node (H<=8)
__device__ float g_ed[NB * NN * 8];    // alpha_dst per node
__device__ int   g_cnt[NN];
__device__ int   g_fill[NN];
__device__ int   g_rowptr[NN + 1];
__device__ int   g_csr[NE];

__device__ __forceinline__ float lrelu(float v) { return v > 0.f ? v : 0.2f * v; }

// ---------------- CSR build ----------------
__global__ __launch_bounds__(256) void k_zero() {
    int i = blockIdx.x * 256 + threadIdx.x;
    if (i < NN) { g_cnt[i] = 0; g_fill[i] = 0; }
}

__global__ __launch_bounds__(256) void k_hist(const int* __restrict__ ei) {
    int e = blockIdx.x * 256 + threadIdx.x;
    if (e < NE) atomicAdd(&g_cnt[ei[NE + e]], 1);
}

__global__ __launch_bounds__(1024) void k_scan() {
    __shared__ int sh[1024];
    int t = threadIdx.x;
    const int CH = (NN + 1023) / 1024;  // 20
    int base = t * CH;
    int s = 0;
    for (int j = 0; j < CH; j++) {
        int idx = base + j;
        if (idx < NN) s += g_cnt[idx];
    }
    sh[t] = s;
    __syncthreads();
    for (int d = 1; d < 1024; d <<= 1) {
        int v = (t >= d) ? sh[t - d] : 0;
        __syncthreads();
        sh[t] += v;
        __syncthreads();
    }
    int run = sh[t] - s;   // exclusive prefix for this chunk
    for (int j = 0; j < CH; j++) {
        int idx = base + j;
        if (idx < NN) { g_rowptr[idx] = run; run += g_cnt[idx]; }
    }
    if (t == 1023) g_rowptr[NN] = sh[1023];
}

__global__ __launch_bounds__(256) void k_scatter(const int* __restrict__ ei) {
    int e = blockIdx.x * 256 + threadIdx.x;
    if (e < NE) {
        int d = ei[NE + e];
        int pos = g_rowptr[d] + atomicAdd(&g_fill[d], 1);
        g_csr[pos] = ei[e];
    }
}

// sort each node's src list by value -> deterministic accumulation order
__global__ __launch_bounds__(256) void k_sort() {
    __shared__ int buf[8][DEG_CAP];
    int w = threadIdx.x >> 5, lane = threadIdx.x & 31;
    int node = blockIdx.x * 8 + w;
    if (node >= NN) return;
    int start = g_rowptr[node];
    int deg = g_rowptr[node + 1] - start;
    if (deg <= 1) return;
    if (deg <= DEG_CAP) {
        for (int j = lane; j < deg; j += 32) buf[w][j] = g_csr[start + j];
        __syncwarp();
        for (int it = 0; it < deg; ++it) {
            int par = it & 1;
            for (int idx = par + 2 * lane; idx + 1 < deg; idx += 64) {
                int a = buf[w][idx], b = buf[w][idx + 1];
                if (a > b) { buf[w][idx] = b; buf[w][idx + 1] = a; }
            }
            __syncwarp();
        }
        for (int j = lane; j < deg; j += 32) g_csr[start + j] = buf[w][j];
    } else if (lane == 0) {   // statistically impossible fallback (global insertion sort)
        for (int a = start + 1; a < start + deg; a++) {
            int v = g_csr[a];
            int b = a - 1;
            while (b >= start && g_csr[b] > v) { g_csr[b + 1] = g_csr[b]; b--; }
            g_csr[b + 1] = v;
        }
    }
}

// ---------------- input projection: h[b,n,:] = x[b,:,n]^T @ pw + pb ----------------
__global__ __launch_bounds__(256) void k_proj(const float* __restrict__ x,
                                              const float* __restrict__ pw,
                                              const float* __restrict__ pb) {
    __shared__ float w_sh[NS * HD];
    __shared__ float b_sh[HD];
    int tid = threadIdx.x;
    for (int idx = tid; idx < NS * HD; idx += 256) w_sh[idx] = pw[idx];
    if (tid < HD) b_sh[tid] = pb[tid];
    __syncthreads();
    int w = tid >> 5, lane = tid & 31;
    for (int idx = blockIdx.x * 8 + w; idx < NB * NN; idx += gridDim.x * 8) {
        int b = idx / NN, n = idx % NN;
        float a0 = b_sh[lane], a1 = b_sh[lane + 32];
        #pragma unroll
        for (int s = 0; s < NS; s++) {
            float xv = x[(b * NS + s) * NN + n];
            a0 += xv * w_sh[s * HD + lane];
            a1 += xv * w_sh[s * HD + lane + 32];
        }
        size_t base = (size_t)idx * HD;
        g_h[base + lane] = a0;
        g_h[base + lane + 32] = a1;
    }
}

// ---------------- per-layer: xe = h @ W ; es/ed attention dots ----------------
template <int H>
__global__ __launch_bounds__(256) void k_gemm(const float* __restrict__ W,
                                              const float* __restrict__ asrc,
                                              const float* __restrict__ adst) {
    __shared__ float w_sh[HD * HD];
    __shared__ float as_sh[HD], ad_sh[HD];
    int tid = threadIdx.x;
    for (int idx = tid; idx < HD * HD; idx += 256) w_sh[idx] = W[idx];
    if (tid < HD) { as_sh[tid] = asrc[tid]; ad_sh[tid] = adst[tid]; }
    __syncthreads();
    int w = tid >> 5, lane = tid & 31;
    for (int idx = blockIdx.x * 8 + w; idx < NB * NN; idx += gridDim.x * 8) {
        size_t base = (size_t)idx * HD;
        float hlo = g_h[base + lane];
        float hhi = g_h[base + lane + 32];
        float a0 = 0.f, a1 = 0.f;
        #pragma unroll
        for (int k = 0; k < HD; k++) {
            float hk = __shfl_sync(FULL, (k < 32) ? hlo : hhi, k & 31);
            a0 += hk * w_sh[k * HD + lane];
            a1 += hk * w_sh[k * HD + lane + 32];
        }
        g_xe[base + lane] = a0;
        g_xe[base + lane + 32] = a1;
        // attention dots
        float pl = a0 * as_sh[lane], ph = a1 * as_sh[lane + 32];
        float ql = a0 * ad_sh[lane], qh = a1 * ad_sh[lane + 32];
        if (H == 8) {
            #pragma unroll
            for (int d = 1; d < 8; d <<= 1) {
                pl += __shfl_xor_sync(FULL, pl, d);
                ph += __shfl_xor_sync(FULL, ph, d);
                ql += __shfl_xor_sync(FULL, ql, d);
                qh += __shfl_xor_sync(FULL, qh, d);
            }
            if ((lane & 7) == 0) {
                int hh = lane >> 3;
                g_es[(size_t)idx * 8 + hh] = pl;
                g_es[(size_t)idx * 8 + 4 + hh] = ph;
                g_ed[(size_t)idx * 8 + hh] = ql;
                g_ed[(size_t)idx * 8 + 4 + hh] = qh;
            }
        } else {
            float p = pl + ph, q = ql + qh;
            #pragma unroll
            for (int d = 1; d < 32; d <<= 1) {
                p += __shfl_xor_sync(FULL, p, d);
                q += __shfl_xor_sync(FULL, q, d);
            }
            if (lane == 0) { g_es[idx] = p; g_ed[idx] = q; }
        }
    }
}

// ---------------- aggregation: segment softmax + weighted gather, warp per node ----------------
template <int H, bool DO_ELU>
__global__ __launch_bounds__(256) void k_agg(const float* __restrict__ bias) {
    constexpr int SUBS = 32 / H;
    __shared__ int   s_src[8][DEG_CAP];
    __shared__ float s_e[8][DEG_CAP * H];
    int w = threadIdx.x >> 5, lane = threadIdx.x & 31;
    for (int idx = blockIdx.x * 8 + w; idx < NB * NN; idx += gridDim.x * 8) {
        int b = idx / NN, i = idx % NN;
        int bN = b * NN;
        int start = g_rowptr[i];
        int deg = g_rowptr[i + 1] - start;
        int tot = deg + 1;  // + self loop
        int head_lo = (H == 8) ? (lane >> 3) : 0;
        int head_hi = (H == 8) ? 4 + (lane >> 3) : 0;
        float acc_lo = 0.f, acc_hi = 0.f, sum_lo, sum_hi;

        if (tot <= DEG_CAP) {
            for (int j = lane; j < tot; j += 32)
                s_src[w][j] = (j < deg) ? g_csr[start + j] : i;
            __syncwarp();
            // phase 1: logits (packed lanes = SUBS edges x H heads), running max
            int sub = lane / H, h = lane % H;
            float edv = g_ed[(size_t)idx * H + h];
            float m = -3.4e38f;
            for (int j = sub; j < tot; j += SUBS) {
                int s = s_src[w][j];
                float e = lrelu(g_es[(size_t)(bN + s) * H + h] + edv);
                s_e[w][j * H + h] = e;
                m = fmaxf(m, e);
            }
            #pragma unroll
            for (int d = H; d < 32; d <<= 1) m = fmaxf(m, __shfl_xor_sync(FULL, m, d));
            __syncwarp();
            // phase 2: exp (fully packed), running sum
            float sum = 0.f;
            for (int j = sub; j < tot; j += SUBS) {
                float p = __expf(s_e[w][j * H + h] - m);
                s_e[w][j * H + h] = p;
                sum += p;
            }
            #pragma unroll
            for (int d = H; d < 32; d <<= 1) sum += __shfl_xor_sync(FULL, sum, d);
            __syncwarp();
            sum_lo = __shfl_sync(FULL, sum, head_lo);
            sum_hi = __shfl_sync(FULL, sum, head_hi);
            // phase 3: channel-parallel weighted gather (coalesced xe reads)
            #pragma unroll 4
            for (int j = 0; j < tot; j++) {
                int s = s_src[w][j];
                const float* xr = &g_xe[(size_t)(bN + s) * HD];
                acc_lo += s_e[w][j * H + head_lo] * xr[lane];
                acc_hi += s_e[w][j * H + head_hi] * xr[lane + 32];
            }
        } else {
            // safety fallback (never taken for this graph size)
            float edl = g_ed[(size_t)idx * H + head_lo];
            float edh = g_ed[(size_t)idx * H + head_hi];
            float m_lo = -3.4e38f, m_hi = -3.4e38f;
            for (int j = 0; j < tot; j++) {
                int s = (j < deg) ? g_csr[start + j] : i;
                m_lo = fmaxf(m_lo, lrelu(g_es[(size_t)(bN + s) * H + head_lo] + edl));
                m_hi = fmaxf(m_hi, lrelu(g_es[(size_t)(bN + s) * H + head_hi] + edh));
            }
            sum_lo = 0.f; sum_hi = 0.f;
            for (int j = 0; j < tot; j++) {
                int s = (j < deg) ? g_csr[start + j] : i;
                const float* xr = &g_xe[(size_t)(bN + s) * HD];
                float plo = __expf(lrelu(g_es[(size_t)(bN + s) * H + head_lo] + edl) - m_lo);
                float phi = __expf(lrelu(g_es[(size_t)(bN + s) * H + head_hi] + edh) - m_hi);
                sum_lo += plo; sum_hi += phi;
                acc_lo += plo * xr[lane];
                acc_hi += phi * xr[lane + 32];
            }
        }
        float out_lo = acc_lo / sum_lo + bias[lane];
        float out_hi = acc_hi / sum_hi + bias[lane + 32];
        if (DO_ELU) {
            out_lo = out_lo > 0.f ? out_lo : expm1f(out_lo);
            out_hi = out_hi > 0.f ? out_hi : expm1f(out_hi);
        }
        size_t base = (size_t)idx * HD;
        g_h[base + lane] = out_lo;
        g_h[base + lane + 32] = out_hi;
        __syncwarp();
    }
}

// ---------------- conv1d(k=3) over node dim + relu + linear head ----------------
#define CONV_W_F   (192 * 65)     // padded [i*3+k][o]
#define CONV_H_F   (66 * 64)
#define CONV_SMEM  ((CONV_W_F + CONV_H_F + 192 + 64) * 4)

__global__ __launch_bounds__(256) void k_conv(const float* __restrict__ cw,
                                              const float* __restrict__ cb,
                                              const float* __restrict__ ow,
                                              const float* __restrict__ ob,
                                              float* __restrict__ out) {
    extern __shared__ float sm[];
    float* w_sh = sm;                        // [(i*3+k)*65 + o]
    float* hsh  = w_sh + CONV_W_F;           // 66 rows x 64
    float* ow_sh = hsh + CONV_H_F;           // [o*3+p]
    float* cb_sh = ow_sh + 192;
    int tid = threadIdx.x;
    // transpose-load conv_w: global coalesced, shared conflict-free (pad 65)
    for (int idx = tid; idx < 64 * 192; idx += 256) {
        int o = idx / 192, r = idx % 192;
        w_sh[r * 65 + o] = cw[idx];
    }
    int b = blockIdx.y;
    int n0 = blockIdx.x * 64;
    for (int idx = tid; idx < 66 * 64; idx += 256) {
        int r = idx / 64, c = idx % 64;
        int g = n0 - 1 + r;
        hsh[idx] = (g >= 0 && g < NN) ? g_h[((size_t)(b * NN + g)) * HD + c] : 0.f;
    }
    if (tid < 192) ow_sh[tid] = ow[tid];
    if (tid < 64) cb_sh[tid] = cb[tid];
    __syncthreads();
    int w = tid >> 5, lane = tid & 31;
    float ob0 = ob[0], ob1 = ob[1], ob2 = ob[2];
    for (int pair = 0; pair < 4; pair++) {
        int lnA = w * 8 + pair * 2;
        int nA = n0 + lnA;
        float aAl = cb_sh[lane], aAh = cb_sh[lane + 32];
        float aBl = aAl, aBh = aAh;
        #pragma unroll
        for (int k = 0; k < 3; k++) {
            #pragma unroll 16
            for (int i = 0; i < 64; i++) {
                float wl = w_sh[(i * 3 + k) * 65 + lane];
                float wh = w_sh[(i * 3 + k) * 65 + 32 + lane];
                float hA = hsh[(lnA + k) * 64 + i];
                float hB = hsh[(lnA + 1 + k) * 64 + i];
                aAl += hA * wl; aAh += hA * wh;
                aBl += hB * wl; aBh += hB * wh;
            }
        }
        aAl = fmaxf(aAl, 0.f); aAh = fmaxf(aAh, 0.f);
        aBl = fmaxf(aBl, 0.f); aBh = fmaxf(aBh, 0.f);
        #pragma unroll
        for (int p = 0; p < 3; p++) {
            float vA = aAl * ow_sh[lane * 3 + p] + aAh * ow_sh[(lane + 32) * 3 + p];
            float vB = aBl * ow_sh[lane * 3 + p] + aBh * ow_sh[(lane + 32) * 3 + p];
            #pragma unroll
            for (int d = 16; d; d >>= 1) {
                vA += __shfl_xor_sync(FULL, vA, d);
                vB += __shfl_xor_sync(FULL, vB, d);
            }
            if (lane == 0) {
                float obp = (p == 0) ? ob0 : (p == 1 ? ob1 : ob2);
                if (nA < NN)     out[(size_t)(b * 3 + p) * NN + nA]     = vA + obp;
                if (nA + 1 < NN) out[(size_t)(b * 3 + p) * NN + nA + 1] = vB + obp;
            }
        }
    }
}

// ---------------- driver ----------------
extern "C" void kernel_launch(void* const* d_in, const int* in_sizes, int n_in,
                              void* d_out, int out_size) {
    const float* x    = (const float*)d_in[0];
    const int*   ei   = (const int*)d_in[1];
    const float* pw   = (const float*)d_in[2];
    const float* pb   = (const float*)d_in[3];
    const float* g0w  = (const float*)d_in[4];
    const float* g0as = (const float*)d_in[5];
    const float* g0ad = (const float*)d_in[6];
    const float* g0b  = (const float*)d_in[7];
    const float* g1w  = (const float*)d_in[8];
    const float* g1as = (const float*)d_in[9];
    const float* g1ad = (const float*)d_in[10];
    const float* g1b  = (const float*)d_in[11];
    const float* g2w  = (const float*)d_in[12];
    const float* g2as = (const float*)d_in[13];
    const float* g2ad = (const float*)d_in[14];
    const float* g2b  = (const float*)d_in[15];
    const float* cw   = (const float*)d_in[16];
    const float* cb   = (const float*)d_in[17];
    const float* ow   = (const float*)d_in[18];
    const float* ob   = (const float*)d_in[19];
    float* out = (float*)d_out;

    // CSR build (deterministic: atomic scatter then per-node value sort)
    k_zero<<<(NN + 255) / 256, 256>>>();
    k_hist<<<(NE + 255) / 256, 256>>>(ei);
    k_scan<<<1, 1024>>>();
    k_scatter<<<(NE + 255) / 256, 256>>>(ei);
    k_sort<<<(NN + 7) / 8, 256>>>();

    k_proj<<<1250, 256>>>(x, pw, pb);

    k_gemm<8><<<1250, 256>>>(g0w, g0as, g0ad);
    k_agg<8, true><<<2500, 256>>>(g0b);
    k_gemm<8><<<1250, 256>>>(g1w, g1as, g1ad);
    k_agg<8, true><<<2500, 256>>>(g1b);
    k_gemm<1><<<1250, 256>>>(g2w, g2as, g2ad);
    k_agg<1, false><<<2500, 256>>>(g2b);

    cudaFuncSetAttribute(k_conv, cudaFuncAttributeMaxDynamicSharedMemorySize, CONV_SMEM);
    k_conv<<<dim3((NN + 63) / 64, NB), 256, CONV_SMEM>>>(cw, cb, ow, ob, out);
}

// round 2
// speedup vs baseline: 1.4211x; 1.4211x over previous
#include <cuda_runtime.h>
#include <cuda_fp16.h>
#include <math.h>

#define NN 20000
#define NE 640000
#define NB 4
#define NS 12
#define HD 64
#define DEG_CAP 128
#define FULL 0xffffffffu

// ---------------- scratch (static device globals; no allocs) ----------------
__device__ float   g_h [NB * NN * HD];    // node features (fp32, channel-natural)
__device__ __half2 g_xeh[NB * NN * 32];   // transformed features, half2 per channel pair
__device__ float   g_es[NB * NN * 8];     // alpha_src per node (H<=8)
__device__ float   g_ed[NB * NN * 8];     // alpha_dst per node
__device__ int     g_cnt[NN];
__device__ int     g_fill[NN];
__device__ int     g_rowptr[NN + 1];
__device__ int     g_csr[NE];

__device__ __forceinline__ float lrelu(float v) { return v > 0.f ? v : 0.2f * v; }

// packed f32x2 FMA: acc += w * (h, h)
__device__ __forceinline__ void ffma2(float2& acc, float2 w, float h) {
    unsigned long long* pa = reinterpret_cast<unsigned long long*>(&acc);
    unsigned long long  pw = *reinterpret_cast<unsigned long long*>(&w);
    asm("{\n\t.reg .b64 hh;\n\tmov.b64 hh, {%1, %1};\n\tfma.rn.f32x2 %0, %2, hh, %0;\n\t}"
        : "+l"(*pa) : "f"(h), "l"(pw));
}

// ---------------- CSR build ----------------
__global__ __launch_bounds__(256) void k_zero() {
    int i = blockIdx.x * 256 + threadIdx.x;
    if (i < NN) { g_cnt[i] = 0; g_fill[i] = 0; }
}

__global__ __launch_bounds__(256) void k_hist(const int* __restrict__ ei) {
    int e = blockIdx.x * 256 + threadIdx.x;
    if (e < NE) atomicAdd(&g_cnt[ei[NE + e]], 1);
}

__global__ __launch_bounds__(1024) void k_scan() {
    __shared__ int sh[1024];
    int t = threadIdx.x;
    const int CH = (NN + 1023) / 1024;  // 20
    int base = t * CH;
    int s = 0;
    for (int j = 0; j < CH; j++) {
        int idx = base + j;
        if (idx < NN) s += g_cnt[idx];
    }
    sh[t] = s;
    __syncthreads();
    for (int d = 1; d < 1024; d <<= 1) {
        int v = (t >= d) ? sh[t - d] : 0;
        __syncthreads();
        sh[t] += v;
        __syncthreads();
    }
    int run = sh[t] - s;
    for (int j = 0; j < CH; j++) {
        int idx = base + j;
        if (idx < NN) { g_rowptr[idx] = run; run += g_cnt[idx]; }
    }
    if (t == 1023) g_rowptr[NN] = sh[1023];
}

__global__ __launch_bounds__(256) void k_scatter(const int* __restrict__ ei) {
    int e = blockIdx.x * 256 + threadIdx.x;
    if (e < NE) {
        int d = ei[NE + e];
        int pos = g_rowptr[d] + atomicAdd(&g_fill[d], 1);
        g_csr[pos] = ei[e];
    }
}

// sort each node's src list by value -> deterministic accumulation order
__global__ __launch_bounds__(256) void k_sort() {
    __shared__ int buf[8][DEG_CAP];
    int w = threadIdx.x >> 5, lane = threadIdx.x & 31;
    int node = blockIdx.x * 8 + w;
    if (node >= NN) return;
    int start = g_rowptr[node];
    int deg = g_rowptr[node + 1] - start;
    if (deg <= 1) return;
    if (deg <= DEG_CAP) {
        for (int j = lane; j < deg; j += 32) buf[w][j] = g_csr[start + j];
        __syncwarp();
        for (int it = 0; it < deg; ++it) {
            int par = it & 1;
            for (int idx = par + 2 * lane; idx + 1 < deg; idx += 64) {
                int a = buf[w][idx], b = buf[w][idx + 1];
                if (a > b) { buf[w][idx] = b; buf[w][idx + 1] = a; }
            }
            __syncwarp();
        }
        for (int j = lane; j < deg; j += 32) g_csr[start + j] = buf[w][j];
    } else if (lane == 0) {   // statistically impossible fallback
        for (int a = start + 1; a < start + deg; a++) {
            int v = g_csr[a];
            int b = a - 1;
            while (b >= start && g_csr[b] > v) { g_csr[b + 1] = g_csr[b]; b--; }
            g_csr[b + 1] = v;
        }
    }
}

// ---------------- shared gemm tail: xe = h @ W; es/ed dots ----------------
// lane owns channels (2l, 2l+1); h[r] holds node r's pair.
template <int H>
__device__ __forceinline__ void gemm_body(int idx0, int lane, const float2 h[4],
                                          const float2* w_sh, const float2* as_sh,
                                          const float2* ad_sh) {
    float2 acc[4];
    #pragma unroll
    for (int r = 0; r < 4; r++) acc[r] = make_float2(0.f, 0.f);
    #pragma unroll
    for (int kk = 0; kk < 32; kk++) {
        float2 wa = w_sh[(2 * kk) * 32 + lane];
        float2 wb = w_sh[(2 * kk + 1) * 32 + lane];
        #pragma unroll
        for (int r = 0; r < 4; r++) {
            float hx = __shfl_sync(FULL, h[r].x, kk);
            float hy = __shfl_sync(FULL, h[r].y, kk);
            ffma2(acc[r], wa, hx);
            ffma2(acc[r], wb, hy);
        }
    }
    #pragma unroll
    for (int r = 0; r < 4; r++) {
        int idx = idx0 + r;
        g_xeh[(size_t)idx * 32 + lane] = __floats2half2_rn(acc[r].x, acc[r].y);
        float p = acc[r].x * as_sh[lane].x + acc[r].y * as_sh[lane].y;
        float q = acc[r].x * ad_sh[lane].x + acc[r].y * ad_sh[lane].y;
        if (H == 8) {
            p += __shfl_xor_sync(FULL, p, 1); p += __shfl_xor_sync(FULL, p, 2);
            q += __shfl_xor_sync(FULL, q, 1); q += __shfl_xor_sync(FULL, q, 2);
            if ((lane & 3) == 0) {
                g_es[(size_t)idx * 8 + (lane >> 2)] = p;
                g_ed[(size_t)idx * 8 + (lane >> 2)] = q;
            }
        } else {
            #pragma unroll
            for (int d = 1; d < 32; d <<= 1) {
                p += __shfl_xor_sync(FULL, p, d);
                q += __shfl_xor_sync(FULL, q, d);
            }
            if (lane == 0) { g_es[idx] = p; g_ed[idx] = q; }
        }
    }
}

template <int H>
__global__ __launch_bounds__(256) void k_gemm(const float* __restrict__ W,
                                              const float* __restrict__ asrc,
                                              const float* __restrict__ adst) {
    __shared__ float2 w_sh[64 * 32];
    __shared__ float2 as_sh[32], ad_sh[32];
    int tid = threadIdx.x;
    const float2* W2 = (const float2*)W;
    for (int i = tid; i < 2048; i += 256) w_sh[i] = W2[i];
    if (tid < 32) {
        as_sh[tid] = ((const float2*)asrc)[tid];
        ad_sh[tid] = ((const float2*)adst)[tid];
    }
    __syncthreads();
    int w = tid >> 5, lane = tid & 31;
    int idx0 = (blockIdx.x * 8 + w) * 4;
    const float2* __restrict__ gh2 = (const float2*)g_h;
    float2 h[4];
    #pragma unroll
    for (int r = 0; r < 4; r++) h[r] = gh2[(size_t)(idx0 + r) * 32 + lane];
    gemm_body<H>(idx0, lane, h, w_sh, as_sh, ad_sh);
}

// fused projection + gemm0 (skips the g_h round trip for layer 0)
__global__ __launch_bounds__(256) void k_proj_gemm(const float* __restrict__ x,
                                                   const float* __restrict__ pw,
                                                   const float* __restrict__ pb,
                                                   const float* __restrict__ W,
                                                   const float* __restrict__ asrc,
                                                   const float* __restrict__ adst) {
    __shared__ float2 w_sh[64 * 32];
    __shared__ float2 pw_sh[NS * 32];
    __shared__ float2 pb_sh[32];
    __shared__ float2 as_sh[32], ad_sh[32];
    int tid = threadIdx.x;
    const float2* W2 = (const float2*)W;
    for (int i = tid; i < 2048; i += 256) w_sh[i] = W2[i];
    for (int i = tid; i < NS * 32; i += 256) pw_sh[i] = ((const float2*)pw)[i];
    if (tid < 32) {
        pb_sh[tid] = ((const float2*)pb)[tid];
        as_sh[tid] = ((const float2*)asrc)[tid];
        ad_sh[tid] = ((const float2*)adst)[tid];
    }
    __syncthreads();
    int w = tid >> 5, lane = tid & 31;
    int idx0 = (blockIdx.x * 8 + w) * 4;
    int b = idx0 / NN, n0 = idx0 % NN;   // NN % 4 == 0 -> same b for all 4
    float2 h[4];
    #pragma unroll
    for (int r = 0; r < 4; r++) {
        float2 hh = pb_sh[lane];
        #pragma unroll
        for (int s = 0; s < NS; s++) {
            float xs = __ldg(&x[(size_t)(b * NS + s) * NN + n0 + r]);
            ffma2(hh, pw_sh[s * 32 + lane], xs);
        }
        h[r] = hh;
    }
    gemm_body<8>(idx0, lane, h, w_sh, as_sh, ad_sh);
}

// ---------------- aggregation: segment softmax + fp16 weighted gather ----------------
template <int H, bool DO_ELU>
__global__ __launch_bounds__(256) void k_agg(const float* __restrict__ bias) {
    constexpr int SUBS = 32 / H;
    __shared__ int   s_src[8][DEG_CAP];
    __shared__ float s_e[8][DEG_CAP * H];
    int w = threadIdx.x >> 5, lane = threadIdx.x & 31;
    int idx = blockIdx.x * 8 + w;          // grid = NB*NN/8 exactly
    int b = idx / NN, i = idx % NN;
    int bN = b * NN;
    int start = g_rowptr[i];
    int deg = g_rowptr[i + 1] - start;
    int tot = deg + 1;                     // + self loop
    int hd = (H == 8) ? (lane >> 2) : 0;   // head of this lane's channel pair
    float2 acc = make_float2(0.f, 0.f);
    float sumv;

    if (tot <= DEG_CAP) {
        for (int j = lane; j < tot; j += 32)
            s_src[w][j] = (j < deg) ? g_csr[start + j] : i;
        __syncwarp();
        // phase 1: logits (packed lanes = SUBS edges x H heads), running max
        int sub = lane / H, hh = lane % H;
        float edv = g_ed[(size_t)idx * H + hh];
        float m = -3.4e38f;
        for (int j = sub; j < tot; j += SUBS) {
            float e = lrelu(g_es[(size_t)(bN + s_src[w][j]) * H + hh] + edv);
            s_e[w][j * H + hh] = e;
            m = fmaxf(m, e);
        }
        #pragma unroll
        for (int d = H; d < 32; d <<= 1) m = fmaxf(m, __shfl_xor_sync(FULL, m, d));
        __syncwarp();
        // phase 2: exp (fully packed), running sum
        float sum = 0.f;
        for (int j = sub; j < tot; j += SUBS) {
            float p = __expf(s_e[w][j * H + hh] - m);
            s_e[w][j * H + hh] = p;
            sum += p;
        }
        #pragma unroll
        for (int d = H; d < 32; d <<= 1) sum += __shfl_xor_sync(FULL, sum, d);
        __syncwarp();
        sumv = (H == 8) ? __shfl_sync(FULL, sum, lane >> 2) : sum;
        // phase 3: channel-parallel fp16 gather (128B coalesced per edge)
        #pragma unroll 4
        for (int j = 0; j < tot; j++) {
            int s = s_src[w][j];
            float p = s_e[w][j * H + hd];
            float2 f = __half22float2(g_xeh[(size_t)(bN + s) * 32 + lane]);
            ffma2(acc, f, p);
        }
    } else {
        // safety fallback (never taken for this graph)
        float edv = g_ed[(size_t)idx * H + hd];
        float m = -3.4e38f;
        for (int j = 0; j < tot; j++) {
            int s = (j < deg) ? g_csr[start + j] : i;
            m = fmaxf(m, lrelu(g_es[(size_t)(bN + s) * H + hd] + edv));
        }
        sumv = 0.f;
        for (int j = 0; j < tot; j++) {
            int s = (j < deg) ? g_csr[start + j] : i;
            float p = __expf(lrelu(g_es[(size_t)(bN + s) * H + hd] + edv) - m);
            sumv += p;
            float2 f = __half22float2(g_xeh[(size_t)(bN + s) * 32 + lane]);
            ffma2(acc, f, p);
        }
    }
    float2 bb = ((const float2*)bias)[lane];
    float ox = acc.x / sumv + bb.x;
    float oy = acc.y / sumv + bb.y;
    if (DO_ELU) {
        ox = ox > 0.f ? ox : expm1f(ox);
        oy = oy > 0.f ? oy : expm1f(oy);
    }
    ((float2*)g_h)[(size_t)idx * 32 + lane] = make_float2(ox, oy);
}

// ---------------- conv1d(k=3) over node dim + relu + linear head ----------------
#define CONV_W_F   (192 * 66)     // padded [r=i*3+k][o], float2-readable
#define CONV_H_F   (66 * 64)
#define CONV_SMEM  ((CONV_W_F + CONV_H_F + 192 + 64) * 4)

__global__ __launch_bounds__(256) void k_conv(const float* __restrict__ cw,
                                              const float* __restrict__ cb,
                                              const float* __restrict__ ow,
                                              const float* __restrict__ ob,
                                              float* __restrict__ out) {
    extern __shared__ float sm[];
    float* w_sh  = sm;                       // [r*66 + o]
    float* hsh   = w_sh + CONV_W_F;          // 66 rows x 64 ch
    float* ow_sh = hsh + CONV_H_F;           // [o*3 + p]
    float* cb_sh = ow_sh + 192;
    int tid = threadIdx.x;
    for (int idx = tid; idx < 64 * 192; idx += 256) {
        int o = idx / 192, r = idx % 192;
        w_sh[r * 66 + o] = cw[idx];
    }
    int b = blockIdx.y;
    int n0 = blockIdx.x * 64;
    float4* hsh4 = (float4*)hsh;
    const float4* gh4 = (const float4*)g_h;
    for (int idx = tid; idx < 66 * 16; idx += 256) {
        int row = idx / 16, c4 = idx % 16;
        int g = n0 - 1 + row;
        hsh4[idx] = (g >= 0 && g < NN) ? gh4[(size_t)(b * NN + g) * 16 + c4]
                                       : make_float4(0.f, 0.f, 0.f, 0.f);
    }
    if (tid < 192) ow_sh[tid] = ow[tid];
    if (tid < 64) cb_sh[tid] = cb[tid];
    __syncthreads();
    int w = tid >> 5, lane = tid & 31;
    float2 cb2 = ((float2*)cb_sh)[lane];
    float ob0 = ob[0], ob1 = ob[1], ob2 = ob[2];
    for (int g4 = 0; g4 < 2; g4++) {
        int ln = w * 8 + g4 * 4;             // local row of first node in group
        float2 acc[4];
        #pragma unroll
        for (int r = 0; r < 4; r++) acc[r] = cb2;
        #pragma unroll
        for (int k = 0; k < 3; k++) {
            #pragma unroll 2
            for (int i4 = 0; i4 < 16; i4++) {
                float4 h4[4];
                #pragma unroll
                for (int r = 0; r < 4; r++) h4[r] = hsh4[(ln + r + k) * 16 + i4];
                #pragma unroll
                for (int u = 0; u < 4; u++) {
                    float2 wv = ((float2*)(w_sh + (size_t)((i4 * 4 + u) * 3 + k) * 66))[lane];
                    #pragma unroll
                    for (int r = 0; r < 4; r++) {
                        float hv = (u == 0) ? h4[r].x : (u == 1) ? h4[r].y
                                 : (u == 2) ? h4[r].z : h4[r].w;
                        ffma2(acc[r], wv, hv);
                    }
                }
            }
        }
        #pragma unroll
        for (int r = 0; r < 4; r++) {
            float ax = fmaxf(acc[r].x, 0.f);
            float ay = fmaxf(acc[r].y, 0.f);
            int n = n0 + ln + r;
            #pragma unroll
            for (int p = 0; p < 3; p++) {
                float v = ax * ow_sh[(2 * lane) * 3 + p] + ay * ow_sh[(2 * lane + 1) * 3 + p];
                #pragma unroll
                for (int d = 16; d; d >>= 1) v += __shfl_xor_sync(FULL, v, d);
                if (lane == 0 && n < NN) {
                    float obp = (p == 0) ? ob0 : (p == 1 ? ob1 : ob2);
                    out[(size_t)(b * 3 + p) * NN + n] = v + obp;
                }
            }
        }
    }
}

// ---------------- driver ----------------
extern "C" void kernel_launch(void* const* d_in, const int* in_sizes, int n_in,
                              void* d_out, int out_size) {
    const float* x    = (const float*)d_in[0];
    const int*   ei   = (const int*)d_in[1];
    const float* pw   = (const float*)d_in[2];
    const float* pb   = (const float*)d_in[3];
    const float* g0w  = (const float*)d_in[4];
    const float* g0as = (const float*)d_in[5];
    const float* g0ad = (const float*)d_in[6];
    const float* g0b  = (const float*)d_in[7];
    const float* g1w  = (const float*)d_in[8];
    const float* g1as = (const float*)d_in[9];
    const float* g1ad = (const float*)d_in[10];
    const float* g1b  = (const float*)d_in[11];
    const float* g2w  = (const float*)d_in[12];
    const float* g2as = (const float*)d_in[13];
    const float* g2ad = (const float*)d_in[14];
    const float* g2b  = (const float*)d_in[15];
    const float* cw   = (const float*)d_in[16];
    const float* cb   = (const float*)d_in[17];
    const float* ow   = (const float*)d_in[18];
    const float* ob   = (const float*)d_in[19];
    float* out = (float*)d_out;

    k_zero<<<(NN + 255) / 256, 256>>>();
    k_hist<<<(NE + 255) / 256, 256>>>(ei);
    k_scan<<<1, 1024>>>();
    k_scatter<<<(NE + 255) / 256, 256>>>(ei);
    k_sort<<<(NN + 7) / 8, 256>>>();

    k_proj_gemm<<<NB * NN / 32, 256>>>(x, pw, pb, g0w, g0as, g0ad);
    k_agg<8, true><<<NB * NN / 8, 256>>>(g0b);
    k_gemm<8><<<NB * NN / 32, 256>>>(g1w, g1as, g1ad);
    k_agg<8, true><<<NB * NN / 8, 256>>>(g1b);
    k_gemm<1><<<NB * NN / 32, 256>>>(g2w, g2as, g2ad);
    k_agg<1, false><<<NB * NN / 8, 256>>>(g2b);

    cudaFuncSetAttribute(k_conv, cudaFuncAttributeMaxDynamicSharedMemorySize, CONV_SMEM);
    k_conv<<<dim3((NN + 63) / 64, NB), 256, CONV_SMEM>>>(cw, cb, ow, ob, out);
}

// round 3
// speedup vs baseline: 1.5634x; 1.1002x over previous
#include <cuda_runtime.h>
#include <cuda_fp16.h>
#include <math.h>

#define NN 20000
#define NE 640000
#define NB 4
#define NS 12
#define HD 64
#define DEG_CAP 96
#define FULL 0xffffffffu

// ---------------- scratch ----------------
__device__ float   g_h [NB * NN * HD];
__device__ __half2 g_xeh[NB * NN * 32];
__device__ float   g_es[NB * NN * 8];
__device__ float   g_ed[NB * NN * 8];
__device__ int     g_cnt[NN];
__device__ int     g_rank[NE];
__device__ int     g_rowptr[NN + 1];
__device__ int     g_csr[NE];

__device__ __forceinline__ float lrelu(float v) { return v > 0.f ? v : 0.2f * v; }

__device__ __forceinline__ unsigned f2tf32(float v) {
    unsigned u;
    asm("cvt.rna.tf32.f32 %0, %1;" : "=r"(u) : "f"(v));
    return u;
}

__device__ __forceinline__ void mma_tf32(float c[4], unsigned a0, unsigned a1,
                                         unsigned a2, unsigned a3,
                                         unsigned b0, unsigned b1) {
    asm("mma.sync.aligned.m16n8k8.row.col.f32.tf32.tf32.f32 "
        "{%0,%1,%2,%3},{%4,%5,%6,%7},{%8,%9},{%0,%1,%2,%3};"
        : "+f"(c[0]), "+f"(c[1]), "+f"(c[2]), "+f"(c[3])
        : "r"(a0), "r"(a1), "r"(a2), "r"(a3), "r"(b0), "r"(b1));
}

// ---------------- CSR build ----------------
__global__ __launch_bounds__(256) void k_zero() {
    int i = blockIdx.x * 256 + threadIdx.x;
    if (i < NN) g_cnt[i] = 0;
}

__global__ __launch_bounds__(256) void k_hist(const int* __restrict__ ei) {
    int e = blockIdx.x * 256 + threadIdx.x;
    if (e < NE) g_rank[e] = atomicAdd(&g_cnt[ei[NE + e]], 1);
}

__global__ __launch_bounds__(1024) void k_scan() {
    __shared__ int sh[1024];
    int t = threadIdx.x;
    const int CH = (NN + 1023) / 1024;
    int base = t * CH;
    int s = 0;
    for (int j = 0; j < CH; j++) {
        int idx = base + j;
        if (idx < NN) s += g_cnt[idx];
    }
    sh[t] = s;
    __syncthreads();
    for (int d = 1; d < 1024; d <<= 1) {
        int v = (t >= d) ? sh[t - d] : 0;
        __syncthreads();
        sh[t] += v;
        __syncthreads();
    }
    int run = sh[t] - s;
    for (int j = 0; j < CH; j++) {
        int idx = base + j;
        if (idx < NN) { g_rowptr[idx] = run; run += g_cnt[idx]; }
    }
    if (t == 1023) g_rowptr[NN] = sh[1023];
}

__global__ __launch_bounds__(256) void k_scatter(const int* __restrict__ ei) {
    int e = blockIdx.x * 256 + threadIdx.x;
    if (e < NE) {
        int d = ei[NE + e];
        g_csr[g_rowptr[d] + g_rank[e]] = ei[e];
    }
}

__global__ __launch_bounds__(256) void k_sort() {
    __shared__ int buf[8][DEG_CAP];
    int w = threadIdx.x >> 5, lane = threadIdx.x & 31;
    int node = blockIdx.x * 8 + w;
    if (node >= NN) return;
    int start = g_rowptr[node];
    int deg = g_rowptr[node + 1] - start;
    if (deg <= 1) return;
    if (deg <= DEG_CAP) {
        for (int j = lane; j < deg; j += 32) buf[w][j] = g_csr[start + j];
        __syncwarp();
        for (int it = 0; it < deg; ++it) {
            int par = it & 1;
            for (int idx = par + 2 * lane; idx + 1 < deg; idx += 64) {
                int a = buf[w][idx], b = buf[w][idx + 1];
                if (a > b) { buf[w][idx] = b; buf[w][idx + 1] = a; }
            }
            __syncwarp();
        }
        for (int j = lane; j < deg; j += 32) g_csr[start + j] = buf[w][j];
    } else if (lane == 0) {   // statistically impossible fallback
        for (int a = start + 1; a < start + deg; a++) {
            int v = g_csr[a];
            int b = a - 1;
            while (b >= start && g_csr[b] > v) { g_csr[b + 1] = g_csr[b]; b--; }
            g_csr[b + 1] = v;
        }
    }
}

// ---------------- gemm body: xe = h @ W; es/ed dots (scalar FFMA, LDS h) ----------------
template <int H>
__device__ __forceinline__ void gemm_body(int idx0, int lane, const float2* hrow,
                                          const float2* w_sh, const float2* as_sh,
                                          const float2* ad_sh) {
    float2 acc[4];
    #pragma unroll
    for (int r = 0; r < 4; r++) acc[r] = make_float2(0.f, 0.f);
    #pragma unroll
    for (int kk = 0; kk < 32; kk++) {
        float2 wa = w_sh[(2 * kk) * 32 + lane];
        float2 wb = w_sh[(2 * kk + 1) * 32 + lane];
        #pragma unroll
        for (int r = 0; r < 4; r++) {
            float2 hp = hrow[r * 32 + kk];   // LDS.64 broadcast
            acc[r].x += hp.x * wa.x; acc[r].y += hp.x * wa.y;
            acc[r].x += hp.y * wb.x; acc[r].y += hp.y * wb.y;
        }
    }
    #pragma unroll
    for (int r = 0; r < 4; r++) {
        int idx = idx0 + r;
        g_xeh[(size_t)idx * 32 + lane] = __floats2half2_rn(acc[r].x, acc[r].y);
        float p = acc[r].x * as_sh[lane].x + acc[r].y * as_sh[lane].y;
        float q = acc[r].x * ad_sh[lane].x + acc[r].y * ad_sh[lane].y;
        if (H == 8) {
            p += __shfl_xor_sync(FULL, p, 1); p += __shfl_xor_sync(FULL, p, 2);
            q += __shfl_xor_sync(FULL, q, 1); q += __shfl_xor_sync(FULL, q, 2);
            if ((lane & 3) == 0) {
                g_es[(size_t)idx * 8 + (lane >> 2)] = p;
                g_ed[(size_t)idx * 8 + (lane >> 2)] = q;
            }
        } else {
            #pragma unroll
            for (int d = 1; d < 32; d <<= 1) {
                p += __shfl_xor_sync(FULL, p, d);
                q += __shfl_xor_sync(FULL, q, d);
            }
            if (lane == 0) { g_es[idx] = p; g_ed[idx] = q; }
        }
    }
}

template <int H>
__global__ __launch_bounds__(256) void k_gemm(const float* __restrict__ W,
                                              const float* __restrict__ asrc,
                                              const float* __restrict__ adst) {
    __shared__ float2 w_sh[64 * 32];
    __shared__ float2 h_sh[8][128];
    __shared__ float2 as_sh[32], ad_sh[32];
    int tid = threadIdx.x;
    const float2* W2 = (const float2*)W;
    for (int i = tid; i < 2048; i += 256) w_sh[i] = W2[i];
    if (tid < 32) {
        as_sh[tid] = ((const float2*)asrc)[tid];
        ad_sh[tid] = ((const float2*)adst)[tid];
    }
    __syncthreads();
    int w = tid >> 5, lane = tid & 31;
    int idx0 = (blockIdx.x * 8 + w) * 4;
    const float2* __restrict__ gh2 = (const float2*)g_h;
    #pragma unroll
    for (int r = 0; r < 4; r++)
        h_sh[w][r * 32 + lane] = gh2[(size_t)(idx0 + r) * 32 + lane];
    __syncwarp();
    gemm_body<H>(idx0, lane, h_sh[w], w_sh, as_sh, ad_sh);
}

// fused projection + gemm0
__global__ __launch_bounds__(256) void k_proj_gemm(const float* __restrict__ x,
                                                   const float* __restrict__ pw,
                                                   const float* __restrict__ pb,
                                                   const float* __restrict__ W,
                                                   const float* __restrict__ asrc,
                                                   const float* __restrict__ adst) {
    __shared__ float2 w_sh[64 * 32];
    __shared__ float2 h_sh[8][128];
    __shared__ float2 pw_sh[NS * 32];
    __shared__ float2 pb_sh[32];
    __shared__ float2 as_sh[32], ad_sh[32];
    int tid = threadIdx.x;
    const float2* W2 = (const float2*)W;
    for (int i = tid; i < 2048; i += 256) w_sh[i] = W2[i];
    for (int i = tid; i < NS * 32; i += 256) pw_sh[i] = ((const float2*)pw)[i];
    if (tid < 32) {
        pb_sh[tid] = ((const float2*)pb)[tid];
        as_sh[tid] = ((const float2*)asrc)[tid];
        ad_sh[tid] = ((const float2*)adst)[tid];
    }
    __syncthreads();
    int w = tid >> 5, lane = tid & 31;
    int idx0 = (blockIdx.x * 8 + w) * 4;
    int b = idx0 / NN, n0 = idx0 % NN;
    #pragma unroll
    for (int r = 0; r < 4; r++) {
        float2 hh = pb_sh[lane];
        #pragma unroll
        for (int s = 0; s < NS; s++) {
            float xs = __ldg(&x[(size_t)(b * NS + s) * NN + n0 + r]);
            hh.x += xs * pw_sh[s * 32 + lane].x;
            hh.y += xs * pw_sh[s * 32 + lane].y;
        }
        h_sh[w][r * 32 + lane] = hh;
    }
    __syncwarp();
    gemm_body<8>(idx0, lane, h_sh[w], w_sh, as_sh, ad_sh);
}

// ---------------- aggregation ----------------
template <int H, bool DO_ELU>
__global__ __launch_bounds__(256) void k_agg(const float* __restrict__ bias) {
    constexpr int SUBS = 32 / H;
    __shared__ int   s_src[8][DEG_CAP];
    __shared__ float s_e[8][DEG_CAP * H];
    int w = threadIdx.x >> 5, lane = threadIdx.x & 31;
    int idx = blockIdx.x * 8 + w;
    int b = idx / NN, i = idx % NN;
    int bN = b * NN;
    int start = g_rowptr[i];
    int deg = g_rowptr[i + 1] - start;
    int tot = deg + 1;                       // + self loop
    int halfid = lane >> 4, q = lane & 15;   // q = channel quad (4q..4q+3)
    int hq = (H == 8) ? (q >> 1) : 0;        // head of this quad
    float4 a4 = make_float4(0.f, 0.f, 0.f, 0.f);
    float sumv;
    const uint2* xb = ((const uint2*)g_xeh) + (size_t)bN * 16;

    if (tot <= DEG_CAP) {
        for (int j = lane; j < tot; j += 32)
            s_src[w][j] = (j < deg) ? g_csr[start + j] : i;
        __syncwarp();
        // phase 1: logits, packed lanes = SUBS edges x H heads
        int sub = lane / H, hh = lane % H;
        float edv = g_ed[(size_t)idx * H + hh];
        float m = -3.4e38f;
        for (int j = sub; j < tot; j += SUBS) {
            float e = lrelu(g_es[(size_t)(bN + s_src[w][j]) * H + hh] + edv);
            s_e[w][j * H + hh] = e;
            m = fmaxf(m, e);
        }
        #pragma unroll
        for (int d = H; d < 32; d <<= 1) m = fmaxf(m, __shfl_xor_sync(FULL, m, d));
        __syncwarp();
        // phase 2: exp + sum
        float sum = 0.f;
        for (int j = sub; j < tot; j += SUBS) {
            float p = __expf(s_e[w][j * H + hh] - m);
            s_e[w][j * H + hh] = p;
            sum += p;
        }
        #pragma unroll
        for (int d = H; d < 32; d <<= 1) sum += __shfl_xor_sync(FULL, sum, d);
        __syncwarp();
        sumv = (H == 8) ? __shfl_sync(FULL, sum, hq) : sum;
        // phase 3: 2 edges per iter; lanes 0-15 even edge, 16-31 odd edge
        for (int j = 0; j < tot; j += 2) {
            int jj = j + halfid;
            float p = 0.f; int s = i;
            if (jj < tot) { s = s_src[w][jj]; p = s_e[w][jj * H + hq]; }
            uint2 v = xb[(size_t)s * 16 + q];
            float2 f0 = __half22float2(*(const __half2*)&v.x);
            float2 f1 = __half22float2(*(const __half2*)&v.y);
            a4.x += f0.x * p; a4.y += f0.y * p;
            a4.z += f1.x * p; a4.w += f1.y * p;
        }
    } else {
        // safety fallback (never taken for this graph)
        float edv = g_ed[(size_t)idx * H + hq];
        float m = -3.4e38f;
        for (int j = 0; j < tot; j++) {
            int s = (j < deg) ? g_csr[start + j] : i;
            m = fmaxf(m, lrelu(g_es[(size_t)(bN + s) * H + hq] + edv));
        }
        float lsum = 0.f;
        for (int j = 0; j < tot; j += 2) {
            int jj = j + halfid;
            float p = 0.f; int s = i;
            if (jj < tot) {
                s = (jj < deg) ? g_csr[start + jj] : i;
                p = __expf(lrelu(g_es[(size_t)(bN + s) * H + hq] + edv) - m);
            }
            lsum += p;
            uint2 v = xb[(size_t)s * 16 + q];
            float2 f0 = __half22float2(*(const __half2*)&v.x);
            float2 f1 = __half22float2(*(const __half2*)&v.y);
            a4.x += f0.x * p; a4.y += f0.y * p;
            a4.z += f1.x * p; a4.w += f1.y * p;
        }
        lsum += __shfl_xor_sync(FULL, lsum, 16);
        sumv = lsum;
    }
    // combine even/odd halves (deterministic order)
    a4.x += __shfl_xor_sync(FULL, a4.x, 16);
    a4.y += __shfl_xor_sync(FULL, a4.y, 16);
    a4.z += __shfl_xor_sync(FULL, a4.z, 16);
    a4.w += __shfl_xor_sync(FULL, a4.w, 16);
    if (lane < 16) {
        float4 bb = ((const float4*)bias)[q];
        float4 o;
        o.x = a4.x / sumv + bb.x;
        o.y = a4.y / sumv + bb.y;
        o.z = a4.z / sumv + bb.z;
        o.w = a4.w / sumv + bb.w;
        if (DO_ELU) {
            o.x = o.x > 0.f ? o.x : expm1f(o.x);
            o.y = o.y > 0.f ? o.y : expm1f(o.y);
            o.z = o.z > 0.f ? o.z : expm1f(o.z);
            o.w = o.w > 0.f ? o.w : expm1f(o.w);
        }
        ((float4*)g_h)[(size_t)idx * 16 + q] = o;
    }
}

// ---------------- conv1d(k=3) + relu + head via tf32 mma ----------------
// im2col GEMM: out[n,o] = sum_{kappa=i*3+k} h[n-1+k][i] * cw[o][kappa]
#define CM 128
#define W_ELE (192 * 65)
#define H_ELE (130 * 65)
#define CONV_SMEM ((W_ELE + H_ELE + 192 + 64) * 4)

__global__ __launch_bounds__(256) void k_conv(const float* __restrict__ cw,
                                              const float* __restrict__ cb,
                                              const float* __restrict__ ow,
                                              const float* __restrict__ ob,
                                              float* __restrict__ out) {
    extern __shared__ unsigned cms[];
    unsigned* w_sh = cms;                  // [kappa*65 + o], tf32
    unsigned* h_sh = w_sh + W_ELE;         // [row*65 + i], tf32; row0 = node n0-1
    float* ow_sh = (float*)(h_sh + H_ELE); // [o*3+p]
    float* cb_sh = ow_sh + 192;
    int tid = threadIdx.x;
    int b = blockIdx.y;
    int n0 = blockIdx.x * CM;

    for (int t = tid; t < 64 * 192; t += 256) {
        int o = t / 192, ka = t % 192;
        w_sh[ka * 65 + o] = f2tf32(cw[t]);
    }
    for (int t = tid; t < 130 * 64; t += 256) {
        int row = t / 64, c = t % 64;
        int n = n0 - 1 + row;
        float v = (n >= 0 && n < NN) ? g_h[((size_t)(b * NN + n)) * 64 + c] : 0.f;
        h_sh[row * 65 + c] = f2tf32(v);
    }
    if (tid < 192) ow_sh[tid] = ow[tid];
    if (tid < 64) cb_sh[tid] = cb[tid];
    __syncthreads();

    int wz = tid >> 5, lane = tid & 31;
    int m0 = wz * 16;
    int g = lane >> 2, tq = lane & 3;
    float c[8][4];
    #pragma unroll
    for (int t = 0; t < 8; t++)
        #pragma unroll
        for (int r = 0; r < 4; r++) c[t][r] = 0.f;

    #pragma unroll 4
    for (int kc = 0; kc < 24; kc++) {
        int ka = kc * 8 + tq;
        int ia = ka / 3, sa = ka % 3;
        int kb = ka + 4;
        int ib = kb / 3, sb = kb % 3;
        unsigned a0 = h_sh[(m0 + g + sa) * 65 + ia];
        unsigned a1 = h_sh[(m0 + g + 8 + sa) * 65 + ia];
        unsigned a2 = h_sh[(m0 + g + sb) * 65 + ib];
        unsigned a3 = h_sh[(m0 + g + 8 + sb) * 65 + ib];
        #pragma unroll
        for (int t = 0; t < 8; t++) {
            unsigned b0 = w_sh[(kc * 8 + tq) * 65 + 8 * t + g];
            unsigned b1 = w_sh[(kc * 8 + tq + 4) * 65 + 8 * t + g];
            mma_tf32(c[t], a0, a1, a2, a3, b0, b1);
        }
    }
    __syncthreads();           // all warps done reading h_sh

    // write relu(conv + cb) into v_sh (reuse h_sh region as float)
    float* v_sh = (float*)h_sh;
    #pragma unroll
    for (int t = 0; t < 8; t++) {
        int n_ = 8 * t + 2 * tq;
        v_sh[(m0 + g) * 65 + n_]     = fmaxf(c[t][0] + cb_sh[n_], 0.f);
        v_sh[(m0 + g) * 65 + n_ + 1] = fmaxf(c[t][1] + cb_sh[n_ + 1], 0.f);
        v_sh[(m0 + g + 8) * 65 + n_]     = fmaxf(c[t][2] + cb_sh[n_], 0.f);
        v_sh[(m0 + g + 8) * 65 + n_ + 1] = fmaxf(c[t][3] + cb_sh[n_ + 1], 0.f);
    }
    __syncthreads();

    // head: out[b,p,n] = relu_row . ow[:,p] + ob[p]
    float ob0 = ob[0], ob1 = ob[1], ob2 = ob[2];
    for (int task = tid; task < CM * 3; task += 256) {
        int mloc = task / 3, p = task % 3;
        int n = n0 + mloc;
        if (n < NN) {
            float acc = (p == 0) ? ob0 : (p == 1 ? ob1 : ob2);
            #pragma unroll 16
            for (int o = 0; o < 64; o++)
                acc += v_sh[mloc * 65 + o] * ow_sh[o * 3 + p];
            out[((size_t)(b * 3 + p)) * NN + n] = acc;
        }
    }
}

// ---------------- driver ----------------
extern "C" void kernel_launch(void* const* d_in, const int* in_sizes, int n_in,
                              void* d_out, int out_size) {
    const float* x    = (const float*)d_in[0];
    const int*   ei   = (const int*)d_in[1];
    const float* pw   = (const float*)d_in[2];
    const float* pb   = (const float*)d_in[3];
    const float* g0w  = (const float*)d_in[4];
    const float* g0as = (const float*)d_in[5];
    const float* g0ad = (const float*)d_in[6];
    const float* g0b  = (const float*)d_in[7];
    const float* g1w  = (const float*)d_in[8];
    const float* g1as = (const float*)d_in[9];
    const float* g1ad = (const float*)d_in[10];
    const float* g1b  = (const float*)d_in[11];
    const float* g2w  = (const float*)d_in[12];
    const float* g2as = (const float*)d_in[13];
    const float* g2ad = (const float*)d_in[14];
    const float* g2b  = (const float*)d_in[15];
    const float* cw   = (const float*)d_in[16];
    const float* cb   = (const float*)d_in[17];
    const float* ow   = (const float*)d_in[18];
    const float* ob   = (const float*)d_in[19];
    float* out = (float*)d_out;

    k_zero<<<(NN + 255) / 256, 256>>>();
    k_hist<<<(NE + 255) / 256, 256>>>(ei);
    k_scan<<<1, 1024>>>();
    k_scatter<<<(NE + 255) / 256, 256>>>(ei);
    k_sort<<<(NN + 7) / 8, 256>>>();

    k_proj_gemm<<<NB * NN / 32, 256>>>(x, pw, pb, g0w, g0as, g0ad);
    k_agg<8, true><<<NB * NN / 8, 256>>>(g0b);
    k_gemm<8><<<NB * NN / 32, 256>>>(g1w, g1as, g1ad);
    k_agg<8, true><<<NB * NN / 8, 256>>>(g1b);
    k_gemm<1><<<NB * NN / 32, 256>>>(g2w, g2as, g2ad);
    k_agg<1, false><<<NB * NN / 8, 256>>>(g2b);

    cudaFuncSetAttribute(k_conv, cudaFuncAttributeMaxDynamicSharedMemorySize, CONV_SMEM);
    k_conv<<<dim3((NN + CM - 1) / CM, NB), 256, CONV_SMEM>>>(cw, cb, ow, ob, out);
}